// round 1
// baseline (speedup 1.0000x reference)
#include <cuda_runtime.h>

#define VOC   96
#define BS    16
#define NQ    200
#define NPTS  25
#define NGT   32
#define LSEQ  25
#define NCOLS (BS*NGT)      /* 512 */
#define CDIM  256
#define QT    8

// ---------------- scratch (static device globals; no allocation) ------------
__device__ float g_soft[VOC*VOC];          // 0.85*I + 0.15*softmax(cn@cn^T)
__device__ float g_T[NCOLS*VOC];           // normalized soft-target dists
__device__ float g_sumTlogT[NCOLS];
__device__ int   g_len[NCOLS];
__device__ float g_logP[BS*NQ*VOC];
__device__ float g_cls[BS*NQ];

// ---------------- fast exp on the FMA pipe (avoids MUFU bottleneck) ---------
__device__ __forceinline__ float fexp(float x) {
    float t = x * 1.4426950408889634f;
    t = fminf(fmaxf(t, -125.0f), 125.0f);
    float n = rintf(t);
    float f = t - n;
    float p = 1.33335581e-3f;
    p = fmaf(p, f, 9.61812911e-3f);
    p = fmaf(p, f, 5.55041087e-2f);
    p = fmaf(p, f, 2.40226507e-1f);
    p = fmaf(p, f, 6.93147180e-1f);
    p = fmaf(p, f, 1.0f);
    int e = (int)n;
    return p * __int_as_float((e + 127) << 23);
}

// ---------------- kernel 1: soft_all [96,96] --------------------------------
__global__ void k_soft(const float* __restrict__ centroids) {
    __shared__ float ci[CDIM];
    __shared__ float srow[VOC];
    __shared__ float erow[VOC];
    __shared__ float s_ni;
    int i = blockIdx.x;
    int t = threadIdx.x;              // 96 threads
    for (int d = t; d < CDIM; d += VOC) ci[d] = centroids[i*CDIM + d];
    __syncthreads();
    const float* cj = centroids + t*CDIM;
    float dot = 0.f, nj = 0.f;
    #pragma unroll 8
    for (int d = 0; d < CDIM; d++) {
        float a = ci[d], b = cj[d];
        dot = fmaf(a, b, dot);
        nj  = fmaf(b, b, nj);
    }
    if (t == i) s_ni = nj;
    __syncthreads();
    float s = dot * rsqrtf(nj * s_ni);
    srow[t] = s;
    __syncthreads();
    float m = -1e30f;
    for (int j = 0; j < VOC; j++) m = fmaxf(m, srow[j]);
    float e = fexp(s - m);
    erow[t] = e;
    __syncthreads();
    float S = 0.f;
    for (int j = 0; j < VOC; j++) S += erow[j];
    g_soft[i*VOC + t] = (t == i ? 0.85f : 0.0f) + 0.15f * (e / S);
}

// ---------------- kernel 2: T, sum T log T, lengths --------------------------
__global__ void k_T(const int* __restrict__ texts) {
    int bg = blockIdx.x;              // 0..511
    int t  = threadIdx.x;             // 96 threads
    __shared__ int   idx[LSEQ];
    __shared__ float red[VOC];
    if (t < LSEQ) idx[t] = texts[bg*LSEQ + t];
    __syncthreads();
    float acc = 0.f; int len = 0;
    #pragma unroll
    for (int l = 0; l < LSEQ; l++) {
        int id = idx[l];
        if (id != VOC) {
            int r = min(max(id, 0), VOC - 1);
            acc += g_soft[r*VOC + t];
            len++;
        }
    }
    float Tv = acc / (float)max(len, 1) + 1e-6f;
    red[t] = Tv;
    __syncthreads();
    float S = 0.f;
    for (int j = 0; j < VOC; j++) S += red[j];
    float Tn = Tv / S;
    g_T[bg*VOC + t] = Tn;
    float tl = Tn * __logf(Tn);
    __syncthreads();
    red[t] = tl;
    __syncthreads();
    if (t == 0) {
        float s2 = 0.f;
        for (int j = 0; j < VOC; j++) s2 += red[j];
        g_sumTlogT[bg] = s2;
        g_len[bg] = len;
    }
}

// ---------------- kernel 3: logP per (b,q) + focal cost_class ----------------
__global__ void __launch_bounds__(128) k_logP(const float* __restrict__ txt,
                                              const float* __restrict__ logits) {
    int bq = blockIdx.x;              // 0..3199
    int t  = threadIdx.x;             // 128 threads
    int w = t >> 5, lane = t & 31;
    __shared__ float E[NPTS*100];     // padded row stride 100
    __shared__ float invZ[NPTS];
    __shared__ float Pv[VOC];
    __shared__ float Ssum;

    const float* X = txt + (size_t)bq * NPTS * (VOC + 1);
    for (int k = t; k < NPTS*(VOC+1); k += 128) {
        int p = k / 97;
        int v = k - p * 97;
        E[p*100 + v] = X[k];
    }
    __syncthreads();

    // per-row softmax: warp per row
    for (int p = w; p < NPTS; p += 4) {
        float x0 = E[p*100 + lane];
        float x1 = E[p*100 + 32 + lane];
        float x2 = E[p*100 + 64 + lane];
        float x3 = (lane == 0) ? E[p*100 + 96] : -1e30f;
        float m = fmaxf(fmaxf(x0, x1), fmaxf(x2, x3));
        #pragma unroll
        for (int o = 16; o; o >>= 1) m = fmaxf(m, __shfl_xor_sync(0xffffffffu, m, o));
        float e0 = fexp(x0 - m), e1 = fexp(x1 - m), e2 = fexp(x2 - m);
        float e3 = (lane == 0) ? fexp(x3 - m) : 0.f;
        float s = e0 + e1 + e2 + e3;
        #pragma unroll
        for (int o = 16; o; o >>= 1) s += __shfl_xor_sync(0xffffffffu, s, o);
        E[p*100 + lane]      = e0;
        E[p*100 + 32 + lane] = e1;
        E[p*100 + 64 + lane] = e2;
        if (lane == 0) { E[p*100 + 96] = e3; invZ[p] = 1.0f / s; }
    }
    __syncthreads();

    float a = 0.f;
    if (t < VOC) {
        #pragma unroll
        for (int p = 0; p < NPTS; p++) a = fmaf(E[p*100 + t], invZ[p], a);
        a = a * (1.0f / 25.0f) + 1e-6f;
        Pv[t] = a;
    }
    // cost_class on warp 3 (lanes 0..24 active)
    float val = 0.f;
    if (t >= 96 && t < 96 + NPTS) {
        float x  = logits[bq*NPTS + (t - 96)];
        float pr = 1.0f / (1.0f + fexp(-x));
        float pos = 0.25f * (1.f - pr) * (1.f - pr) * (-__logf(pr + 1e-8f));
        float neg = 0.75f * pr * pr * (-__logf(1.f - pr + 1e-8f));
        val = pos - neg;
    }
    if (w == 3) {
        #pragma unroll
        for (int o = 16; o; o >>= 1) val += __shfl_xor_sync(0xffffffffu, val, o);
        if (lane == 0) g_cls[bq] = val * (1.0f / 25.0f);
    }
    __syncthreads();
    if (t < 32) {
        float s = Pv[t] + Pv[t + 32] + Pv[t + 64];
        #pragma unroll
        for (int o = 16; o; o >>= 1) s += __shfl_xor_sync(0xffffffffu, s, o);
        if (t == 0) Ssum = s;
    }
    __syncthreads();
    if (t < VOC) g_logP[bq*VOC + t] = __logf(a * (1.0f / Ssum));
}

// ---------------- kernel 4: fused cdist + kl + class -> C --------------------
__global__ void __launch_bounds__(512) k_final(const float* __restrict__ predpts,
                                               const float* __restrict__ tgtpts,
                                               float* __restrict__ out) {
    int b  = blockIdx.y;
    int q0 = blockIdx.x * QT;
    int t  = threadIdx.x;             // 512 threads = one column each

    __shared__ __align__(16) float pp[QT*52];
    __shared__ float lp[QT*VOC];
    __shared__ float Ts[NGT*97];
    __shared__ float stt[NGT];
    __shared__ int   sl[NGT];
    __shared__ float cls[QT];
    __shared__ float kls[QT*NGT];

    for (int k = t; k < QT*50; k += 512) {
        int q = k / 50, d = k - q*50;
        pp[q*52 + d] = predpts[(size_t)(b*NQ + q0 + q)*50 + d];
    }
    for (int k = t; k < QT*VOC; k += 512)
        lp[k] = g_logP[(size_t)(b*NQ + q0)*VOC + k];
    for (int k = t; k < NGT*VOC; k += 512) {
        int g = k / VOC, v = k - g*VOC;
        Ts[g*97 + v] = g_T[(size_t)b*NGT*VOC + k];
    }
    if (t < NGT) { stt[t] = g_sumTlogT[b*NGT + t]; sl[t] = g_len[b*NGT + t]; }
    if (t < QT)  cls[t] = g_cls[b*NQ + q0 + t];
    __syncthreads();

    // kl pre-phase: 256 threads each compute one (q,g) dot over VOC
    if (t < QT*NGT) {
        int q = t >> 5, g = t & 31;
        float d0 = 0.f;
        #pragma unroll 4
        for (int v = 0; v < VOC; v++)
            d0 = fmaf(Ts[g*97 + v], lp[q*VOC + v], d0);
        kls[t] = (sl[g] == 0) ? 100.0f : (stt[g] - d0);
    }

    // per-thread target control points into registers
    float tg[50];
    {
        const float2* src = (const float2*)(tgtpts + (size_t)t * 50);
        #pragma unroll
        for (int i = 0; i < 25; i++) {
            float2 v = src[i];
            tg[2*i] = v.x; tg[2*i + 1] = v.y;
        }
    }
    __syncthreads();

    bool diag = ((t >> 5) == b);
    int  g    = t & 31;
    #pragma unroll
    for (int q = 0; q < QT; q++) {
        float acc = cls[q];
        const float* ppr = &pp[q*52];
        #pragma unroll
        for (int i = 0; i < 12; i++) {
            float4 a = *(const float4*)(ppr + 4*i);
            acc += fabsf(a.x - tg[4*i])     + fabsf(a.y - tg[4*i + 1]);
            acc += fabsf(a.z - tg[4*i + 2]) + fabsf(a.w - tg[4*i + 3]);
        }
        acc += fabsf(ppr[48] - tg[48]) + fabsf(ppr[49] - tg[49]);
        if (diag) acc += kls[q*NGT + g];
        out[(size_t)(b*NQ + q0 + q)*NCOLS + t] = acc;
    }
}

// -----------------------------------------------------------------------------
extern "C" void kernel_launch(void* const* d_in, const int* in_sizes, int n_in,
                              void* d_out, int out_size) {
    const float* pred_logits      = (const float*)d_in[0]; // [16,200,25,1]
    const float* pred_ctrl_points = (const float*)d_in[1]; // [16,200,25,2]
    const float* pred_text_logits = (const float*)d_in[2]; // [16,200,25,97]
    const float* tgt_ctrl_points  = (const float*)d_in[3]; // [16,32,25,2]
    const int*   tgt_texts        = (const int*)d_in[4];   // [16,32,25]
    const float* centroids        = (const float*)d_in[5]; // [96,256]
    float* out = (float*)d_out;                            // [16,200,512]

    k_soft<<<VOC, VOC>>>(centroids);
    k_T<<<NCOLS, VOC>>>(tgt_texts);
    k_logP<<<BS*NQ, 128>>>(pred_text_logits, pred_logits);
    k_final<<<dim3(NQ/QT, BS), 512>>>(pred_ctrl_points, tgt_ctrl_points, out);
}

// round 2
// speedup vs baseline: 1.3847x; 1.3847x over previous
#include <cuda_runtime.h>

#define VOC   96
#define BS    16
#define NQ    200
#define NPTS  25
#define NGT   32
#define LSEQ  25
#define NCOLS (BS*NGT)      /* 512 */
#define CDIM  256
#define QT    8

// ---------------- scratch (static device globals; no allocation) ------------
__device__ float  g_soft[VOC*VOC];          // 0.85*I + 0.15*softmax(cn@cn^T)
__device__ float  g_T[NCOLS*VOC];           // normalized soft-target dists
__device__ float  g_sumTlogT[NCOLS];
__device__ int    g_len[NCOLS];
__device__ float4 g_tgtT4[13*NCOLS];        // transposed+padded tgt pts [dblk][col] -> 4 floats

// ---------------- fast exp on the FMA pipe (avoids MUFU bottleneck) ---------
__device__ __forceinline__ float fexp(float x) {
    float t = x * 1.4426950408889634f;
    t = fminf(fmaxf(t, -125.0f), 125.0f);
    float n = rintf(t);
    float f = t - n;
    float p = 1.33335581e-3f;
    p = fmaf(p, f, 9.61812911e-3f);
    p = fmaf(p, f, 5.55041087e-2f);
    p = fmaf(p, f, 2.40226507e-1f);
    p = fmaf(p, f, 6.93147180e-1f);
    p = fmaf(p, f, 1.0f);
    int e = (int)n;
    return p * __int_as_float((e + 127) << 23);
}

// ---------------- kernel 1: soft_all [96,96] --------------------------------
__global__ void k_soft(const float* __restrict__ centroids) {
    __shared__ float ci[CDIM];
    __shared__ float srow[VOC];
    __shared__ float erow[VOC];
    __shared__ float s_ni;
    int i = blockIdx.x;
    int t = threadIdx.x;              // 96 threads
    for (int d = t; d < CDIM; d += VOC) ci[d] = centroids[i*CDIM + d];
    __syncthreads();
    const float* cj = centroids + t*CDIM;
    float dot = 0.f, nj = 0.f;
    #pragma unroll 8
    for (int d = 0; d < CDIM; d++) {
        float a = ci[d], b = cj[d];
        dot = fmaf(a, b, dot);
        nj  = fmaf(b, b, nj);
    }
    if (t == i) s_ni = nj;
    __syncthreads();
    float s = dot * rsqrtf(nj * s_ni);
    srow[t] = s;
    __syncthreads();
    float m = -1e30f;
    for (int j = 0; j < VOC; j++) m = fmaxf(m, srow[j]);
    float e = fexp(s - m);
    erow[t] = e;
    __syncthreads();
    float S = 0.f;
    for (int j = 0; j < VOC; j++) S += erow[j];
    g_soft[i*VOC + t] = (t == i ? 0.85f : 0.0f) + 0.15f * (e / S);
}

// ---------------- kernel 2: T, sum T log T, lengths, tgt transpose ----------
__global__ void k_T(const int* __restrict__ texts,
                    const float* __restrict__ tgtpts) {
    int bg = blockIdx.x;              // 0..511
    int t  = threadIdx.x;             // 96 threads
    __shared__ int   idx[LSEQ];
    __shared__ float red[VOC];
    if (t < LSEQ) idx[t] = texts[bg*LSEQ + t];
    // transposed/padded tgt control points: tgtT4[dblk*512+col].{x..w}
    if (t < 52) {
        float v = (t < 50) ? tgtpts[bg*50 + t] : 0.0f;
        ((float*)g_tgtT4)[(size_t)((t >> 2)*NCOLS + bg)*4 + (t & 3)] = v;
    }
    __syncthreads();
    float acc = 0.f; int len = 0;
    #pragma unroll
    for (int l = 0; l < LSEQ; l++) {
        int id = idx[l];
        if (id != VOC) {
            int r = min(max(id, 0), VOC - 1);
            acc += g_soft[r*VOC + t];
            len++;
        }
    }
    float Tv = acc / (float)max(len, 1) + 1e-6f;
    red[t] = Tv;
    __syncthreads();
    float S = 0.f;
    for (int j = 0; j < VOC; j++) S += red[j];
    float Tn = Tv / S;
    g_T[bg*VOC + t] = Tn;
    float tl = Tn * __logf(Tn);
    __syncthreads();
    red[t] = tl;
    __syncthreads();
    if (t == 0) {
        float s2 = 0.f;
        for (int j = 0; j < VOC; j++) s2 += red[j];
        g_sumTlogT[bg] = s2;
        g_len[bg] = len;
    }
}

// ---------------- kernel 3: fully fused main kernel --------------------------
// block = (batch b, tile of 8 queries), 512 threads.
// phases: text softmax (2 chunks of 4 q) -> Pv -> logP -> focal -> KL -> cdist
struct __align__(16) SmemMain {
    float E[4*NPTS*97];   // 9700 : chunk of 4 queries, row stride 97
    float invZ[4*NPTS];   // 100
    float Pq[4*VOC];      // 384
    float sS[4];
    float logPs[QT*VOC];  // 768
    float pp[QT*52];      // padded pred pts
    float Ts[NGT*97];     // padded T rows
    float stt[NGT];
    float cls[QT];
    float kls[QT*NGT];
    float fc[QT*NPTS];    // 200
    int   sl[NGT];
};

__global__ void __launch_bounds__(512) k_main(const float* __restrict__ txt,
                                              const float* __restrict__ logits,
                                              const float* __restrict__ predpts,
                                              float* __restrict__ out) {
    extern __shared__ char smraw[];
    SmemMain& s = *reinterpret_cast<SmemMain*>(smraw);
    int b  = blockIdx.y;
    int q0 = blockIdx.x * QT;
    int t  = threadIdx.x;
    int w  = t >> 5, lane = t & 31;

    // ---- preload side data (no dependence on E) ----
    for (int k = t; k < QT*52; k += 512) {
        int q = k / 52, d = k - q*52;
        s.pp[k] = (d < 50) ? predpts[(size_t)(b*NQ + q0 + q)*50 + d] : 0.0f;
    }
    for (int k = t; k < NGT*VOC; k += 512) {
        int g = k / VOC, v = k - g*VOC;
        s.Ts[g*97 + v] = g_T[(size_t)b*NGT*VOC + k];
    }
    if (t < NGT) { s.stt[t] = g_sumTlogT[b*NGT + t]; s.sl[t] = g_len[b*NGT + t]; }
    if (t < QT*NPTS) {
        float x  = logits[(size_t)(b*NQ + q0)*NPTS + t];
        float pr = 1.0f / (1.0f + fexp(-x));
        float pos = 0.25f * (1.f - pr) * (1.f - pr) * (-__logf(pr + 1e-8f));
        float neg = 0.75f * pr * pr * (-__logf(1.f - pr + 1e-8f));
        s.fc[t] = pos - neg;
    }

    // ---- text pipeline: 2 chunks of 4 queries ----
    #pragma unroll 1
    for (int c = 0; c < 2; c++) {
        __syncthreads();   // prior chunk's consumers done before overwriting E
        const float4* src = (const float4*)(txt + (size_t)(b*NQ + q0 + c*4) * NPTS * (VOC + 1));
        #pragma unroll 1
        for (int k = t; k < (4*NPTS*97)/4; k += 512)
            ((float4*)s.E)[k] = src[k];
        __syncthreads();

        // softmax per (q,p): warp per row, 100 rows
        for (int r = w; r < 4*NPTS; r += 16) {
            int base = (r / NPTS)*2425 + (r % NPTS)*97;
            float x0 = s.E[base + lane];
            float x1 = s.E[base + 32 + lane];
            float x2 = s.E[base + 64 + lane];
            float x3 = (lane == 0) ? s.E[base + 96] : -1e30f;
            float m = fmaxf(fmaxf(x0, x1), fmaxf(x2, x3));
            #pragma unroll
            for (int o = 16; o; o >>= 1) m = fmaxf(m, __shfl_xor_sync(0xffffffffu, m, o));
            float e0 = fexp(x0 - m), e1 = fexp(x1 - m), e2 = fexp(x2 - m);
            float e3 = (lane == 0) ? fexp(x3 - m) : 0.f;
            float sm = e0 + e1 + e2 + e3;
            #pragma unroll
            for (int o = 16; o; o >>= 1) sm += __shfl_xor_sync(0xffffffffu, sm, o);
            s.E[base + lane]      = e0;
            s.E[base + 32 + lane] = e1;
            s.E[base + 64 + lane] = e2;
            if (lane == 0) s.invZ[r] = 1.0f / sm;
        }
        __syncthreads();

        // Pv: mean prob over points (+eps)
        if (t < 4*VOC) {
            int q = t / VOC, v = t - q*VOC;
            float a = 0.f;
            #pragma unroll
            for (int p = 0; p < NPTS; p++)
                a = fmaf(s.E[q*2425 + p*97 + v], s.invZ[q*NPTS + p], a);
            s.Pq[t] = a * (1.0f / 25.0f) + 1e-6f;
        }
        __syncthreads();
        if (w < 4) {
            float sm = s.Pq[w*VOC + lane] + s.Pq[w*VOC + 32 + lane] + s.Pq[w*VOC + 64 + lane];
            #pragma unroll
            for (int o = 16; o; o >>= 1) sm += __shfl_xor_sync(0xffffffffu, sm, o);
            if (lane == 0) s.sS[w] = 1.0f / sm;
        }
        __syncthreads();
        if (t < 4*VOC) {
            int q = t / VOC;
            s.logPs[c*4*VOC + t] = __logf(s.Pq[t] * s.sS[q]);
        }
    }
    __syncthreads();

    // ---- cost_class reduce: warp q sums 25 focal values ----
    if (w < QT) {
        float v = (lane < NPTS) ? s.fc[w*NPTS + lane] : 0.f;
        #pragma unroll
        for (int o = 16; o; o >>= 1) v += __shfl_xor_sync(0xffffffffu, v, o);
        if (lane == 0) s.cls[w] = v * (1.0f / 25.0f);
    }
    // ---- KL(q,g) ----
    if (t < QT*NGT) {
        int q = t >> 5, g = t & 31;
        float d0 = 0.f;
        #pragma unroll 8
        for (int v = 0; v < VOC; v++)
            d0 = fmaf(s.Ts[g*97 + v], s.logPs[q*VOC + v], d0);
        s.kls[t] = (s.sl[g] == 0) ? 100.0f : (s.stt[g] - d0);
    }
    __syncthreads();

    // ---- cdist + assemble output: thread t = column ----
    float acc[QT];
    #pragma unroll
    for (int q = 0; q < QT; q++) acc[q] = s.cls[q];
    #pragma unroll
    for (int db = 0; db < 13; db++) {
        float4 tv = g_tgtT4[db*NCOLS + t];   // coalesced, L2/L1 resident
        #pragma unroll
        for (int q = 0; q < QT; q++) {
            float4 a = *(const float4*)&s.pp[q*52 + db*4];
            acc[q] += fabsf(a.x - tv.x) + fabsf(a.y - tv.y)
                    + fabsf(a.z - tv.z) + fabsf(a.w - tv.w);
        }
    }
    bool diag = ((t >> 5) == b);
    int  g    = t & 31;
    #pragma unroll
    for (int q = 0; q < QT; q++) {
        float r = acc[q] + (diag ? s.kls[q*NGT + g] : 0.0f);
        out[(size_t)(b*NQ + q0 + q)*NCOLS + t] = r;
    }
}

// -----------------------------------------------------------------------------
extern "C" void kernel_launch(void* const* d_in, const int* in_sizes, int n_in,
                              void* d_out, int out_size) {
    const float* pred_logits      = (const float*)d_in[0]; // [16,200,25,1]
    const float* pred_ctrl_points = (const float*)d_in[1]; // [16,200,25,2]
    const float* pred_text_logits = (const float*)d_in[2]; // [16,200,25,97]
    const float* tgt_ctrl_points  = (const float*)d_in[3]; // [16,32,25,2]
    const int*   tgt_texts        = (const int*)d_in[4];   // [16,32,25]
    const float* centroids        = (const float*)d_in[5]; // [96,256]
    float* out = (float*)d_out;                            // [16,200,512]

    static bool attr_done = false;
    if (!attr_done) {
        cudaFuncSetAttribute(k_main, cudaFuncAttributeMaxDynamicSharedMemorySize,
                             (int)sizeof(SmemMain));
        attr_done = true;
    }

    k_soft<<<VOC, VOC>>>(centroids);
    k_T<<<NCOLS, VOC>>>(tgt_texts, tgt_ctrl_points);
    k_main<<<dim3(NQ/QT, BS), 512, sizeof(SmemMain)>>>(pred_text_logits, pred_logits,
                                                       pred_ctrl_points, out);
}

// round 3
// speedup vs baseline: 1.6893x; 1.2200x over previous
#include <cuda_runtime.h>

#define VOC   96
#define BS    16
#define NQ    200
#define NPTS  25
#define NGT   32
#define LSEQ  25
#define NCOLS (BS*NGT)      /* 512 */
#define CDIM  256
#define QT    8

typedef unsigned long long u64;
#define ABSM 0x7FFFFFFF7FFFFFFFULL

// ---------------- scratch (static device globals; no allocation) ------------
__device__ float  g_soft[VOC*VOC];
__device__ float  g_T[NCOLS*VOC];
__device__ float  g_sumTlogT[NCOLS];
__device__ int    g_len[NCOLS];
__device__ float4 g_tgtT4[13*NCOLS];        // transposed+padded tgt pts [dblk][col]

// ---------------- packed f32x2 helpers (Blackwell) --------------------------
__device__ __forceinline__ u64 pack2(float lo, float hi) {
    u64 r; asm("mov.b64 %0, {%1, %2};" : "=l"(r) : "f"(lo), "f"(hi)); return r;
}
__device__ __forceinline__ u64 add2(u64 a, u64 b) {
    u64 r; asm("add.rn.f32x2 %0, %1, %2;" : "=l"(r) : "l"(a), "l"(b)); return r;
}
__device__ __forceinline__ void unpack2(float& lo, float& hi, u64 a) {
    asm("mov.b64 {%0, %1}, %2;" : "=f"(lo), "=f"(hi) : "l"(a));
}

// ---------------- fast exp on the FMA pipe -----------------------------------
__device__ __forceinline__ float fexp(float x) {
    float t = x * 1.4426950408889634f;
    t = fminf(fmaxf(t, -125.0f), 125.0f);
    float n = rintf(t);
    float f = t - n;
    float p = 1.33335581e-3f;
    p = fmaf(p, f, 9.61812911e-3f);
    p = fmaf(p, f, 5.55041087e-2f);
    p = fmaf(p, f, 2.40226507e-1f);
    p = fmaf(p, f, 6.93147180e-1f);
    p = fmaf(p, f, 1.0f);
    int e = (int)n;
    return p * __int_as_float((e + 127) << 23);
}

// ---------------- kernel 1: soft_all [96,96], warp-cooperative --------------
__global__ void __launch_bounds__(256) k_soft(const float* __restrict__ centroids) {
    __shared__ float ci[CDIM];
    __shared__ float srow[VOC], nrow[VOC];
    __shared__ float stage[VOC];
    __shared__ float bc[2];
    int i = blockIdx.x, t = threadIdx.x, w = t >> 5, lane = t & 31;

    ci[t] = centroids[i*CDIM + t];
    __syncthreads();

    // warp w computes dots for j = w, w+8, ... (coalesced global loads)
    for (int j = w; j < VOC; j += 8) {
        const float* cj = centroids + j*CDIM;
        float a0 = 0.f, nn = 0.f;
        #pragma unroll
        for (int u = 0; u < 8; u++) {
            float b = cj[lane + u*32];
            float a = ci[lane + u*32];
            a0 = fmaf(a, b, a0);
            nn = fmaf(b, b, nn);
        }
        #pragma unroll
        for (int o = 16; o; o >>= 1) {
            a0 += __shfl_xor_sync(0xffffffffu, a0, o);
            nn += __shfl_xor_sync(0xffffffffu, nn, o);
        }
        if (lane == 0) { srow[j] = a0; nrow[j] = nn; }
    }
    __syncthreads();

    float ni = nrow[i];
    float sv = (t < VOC) ? srow[t] * rsqrtf(nrow[t] * ni) : -1e30f;
    if (t < VOC) stage[t] = sv;
    __syncthreads();
    if (w == 0) {
        float m = fmaxf(fmaxf(stage[lane], stage[lane+32]), stage[lane+64]);
        #pragma unroll
        for (int o = 16; o; o >>= 1) m = fmaxf(m, __shfl_xor_sync(0xffffffffu, m, o));
        if (lane == 0) bc[0] = m;
    }
    __syncthreads();
    float e = (t < VOC) ? fexp(sv - bc[0]) : 0.f;
    if (t < VOC) stage[t] = e;
    __syncthreads();
    if (w == 0) {
        float s = stage[lane] + stage[lane+32] + stage[lane+64];
        #pragma unroll
        for (int o = 16; o; o >>= 1) s += __shfl_xor_sync(0xffffffffu, s, o);
        if (lane == 0) bc[1] = s;
    }
    __syncthreads();
    if (t < VOC)
        g_soft[i*VOC + t] = (t == i ? 0.85f : 0.0f) + 0.15f * (e / bc[1]);
}

// ---------------- kernel 2: T, sum T log T, lengths, tgt transpose ----------
__global__ void k_T(const int* __restrict__ texts,
                    const float* __restrict__ tgtpts) {
    int bg = blockIdx.x;              // 0..511
    int t  = threadIdx.x;             // 96 threads
    __shared__ int   idx[LSEQ];
    __shared__ float red[VOC];
    __shared__ float b0;
    if (t < LSEQ) idx[t] = texts[bg*LSEQ + t];
    if (t < 52) {
        float v = (t < 50) ? tgtpts[bg*50 + t] : 0.0f;
        ((float*)g_tgtT4)[(size_t)((t >> 2)*NCOLS + bg)*4 + (t & 3)] = v;
    }
    __syncthreads();
    float acc = 0.f; int len = 0;
    #pragma unroll
    for (int l = 0; l < LSEQ; l++) {
        int id = idx[l];
        if (id != VOC) {
            int r = min(max(id, 0), VOC - 1);
            acc += g_soft[r*VOC + t];
            len++;
        }
    }
    float Tv = acc / (float)max(len, 1) + 1e-6f;
    red[t] = Tv;
    __syncthreads();
    if (t < 32) {
        float s = red[t] + red[t+32] + red[t+64];
        #pragma unroll
        for (int o = 16; o; o >>= 1) s += __shfl_xor_sync(0xffffffffu, s, o);
        if (t == 0) b0 = s;
    }
    __syncthreads();
    float Tn = Tv / b0;
    g_T[bg*VOC + t] = Tn;
    red[t] = Tn * __logf(Tn);
    __syncthreads();
    if (t < 32) {
        float s2 = red[t] + red[t+32] + red[t+64];
        #pragma unroll
        for (int o = 16; o; o >>= 1) s2 += __shfl_xor_sync(0xffffffffu, s2, o);
        if (t == 0) { g_sumTlogT[bg] = s2; g_len[bg] = len; }
    }
}

// ---------------- kernel 3: fully fused main kernel --------------------------
struct __align__(16) SmemMain {
    float  E[4*NPTS*97];   // 9700
    float  invZ[4*NPTS];
    float  Pq[4*VOC];
    float  sS[4];
    float  logPs[QT*VOC];
    float2 pp2[4*52];      // packed pred pts: pair p holds (q=2p, q=2p+1)
    float  Ts[NGT*97];
    float  stt[NGT];
    float  cls[QT];
    float  kls[QT*NGT];
    float  fc[QT*NPTS];
    int    sl[NGT];
};

__global__ void __launch_bounds__(512) k_main(const float* __restrict__ txt,
                                              const float* __restrict__ logits,
                                              const float* __restrict__ predpts,
                                              float* __restrict__ out) {
    extern __shared__ char smraw[];
    SmemMain& s = *reinterpret_cast<SmemMain*>(smraw);
    int b  = blockIdx.y;
    int q0 = blockIdx.x * QT;
    int t  = threadIdx.x;
    int w  = t >> 5, lane = t & 31;

    // ---- preload side data ----
    for (int k = t; k < 4*52; k += 512) {
        int pair = k / 52, d = k - pair*52;
        float v0 = 0.f, v1 = 0.f;
        if (d < 50) {
            v0 = predpts[(size_t)(b*NQ + q0 + 2*pair)*50 + d];
            v1 = predpts[(size_t)(b*NQ + q0 + 2*pair + 1)*50 + d];
        }
        s.pp2[k] = make_float2(v0, v1);
    }
    for (int k = t; k < NGT*VOC; k += 512) {
        int g = k / VOC, v = k - g*VOC;
        s.Ts[g*97 + v] = g_T[(size_t)b*NGT*VOC + k];
    }
    if (t < NGT) { s.stt[t] = g_sumTlogT[b*NGT + t]; s.sl[t] = g_len[b*NGT + t]; }
    if (t < QT*NPTS) {
        float x  = logits[(size_t)(b*NQ + q0)*NPTS + t];
        float pr = 1.0f / (1.0f + fexp(-x));
        float pos = 0.25f * (1.f - pr) * (1.f - pr) * (-__logf(pr + 1e-8f));
        float neg = 0.75f * pr * pr * (-__logf(1.f - pr + 1e-8f));
        s.fc[t] = pos - neg;
    }

    // ---- text pipeline: 2 chunks of 4 queries ----
    #pragma unroll 1
    for (int c = 0; c < 2; c++) {
        __syncthreads();
        const float4* src = (const float4*)(txt + (size_t)(b*NQ + q0 + c*4) * NPTS * (VOC + 1));
        #pragma unroll 1
        for (int k = t; k < (4*NPTS*97)/4; k += 512)
            ((float4*)s.E)[k] = src[k];
        __syncthreads();

        for (int r = w; r < 4*NPTS; r += 16) {
            int base = (r / NPTS)*2425 + (r % NPTS)*97;
            float x0 = s.E[base + lane];
            float x1 = s.E[base + 32 + lane];
            float x2 = s.E[base + 64 + lane];
            float x3 = (lane == 0) ? s.E[base + 96] : -1e30f;
            float m = fmaxf(fmaxf(x0, x1), fmaxf(x2, x3));
            #pragma unroll
            for (int o = 16; o; o >>= 1) m = fmaxf(m, __shfl_xor_sync(0xffffffffu, m, o));
            float e0 = fexp(x0 - m), e1 = fexp(x1 - m), e2 = fexp(x2 - m);
            float e3 = (lane == 0) ? fexp(x3 - m) : 0.f;
            float sm = e0 + e1 + e2 + e3;
            #pragma unroll
            for (int o = 16; o; o >>= 1) sm += __shfl_xor_sync(0xffffffffu, sm, o);
            s.E[base + lane]      = e0;
            s.E[base + 32 + lane] = e1;
            s.E[base + 64 + lane] = e2;
            if (lane == 0) s.invZ[r] = 1.0f / sm;
        }
        __syncthreads();

        if (t < 4*VOC) {
            int q = t / VOC, v = t - q*VOC;
            float a = 0.f;
            #pragma unroll
            for (int p = 0; p < NPTS; p++)
                a = fmaf(s.E[q*2425 + p*97 + v], s.invZ[q*NPTS + p], a);
            s.Pq[t] = a * (1.0f / 25.0f) + 1e-6f;
        }
        __syncthreads();
        if (w < 4) {
            float sm = s.Pq[w*VOC + lane] + s.Pq[w*VOC + 32 + lane] + s.Pq[w*VOC + 64 + lane];
            #pragma unroll
            for (int o = 16; o; o >>= 1) sm += __shfl_xor_sync(0xffffffffu, sm, o);
            if (lane == 0) s.sS[w] = 1.0f / sm;
        }
        __syncthreads();
        if (t < 4*VOC) {
            int q = t / VOC;
            s.logPs[c*4*VOC + t] = __logf(s.Pq[t] * s.sS[q]);
        }
    }
    __syncthreads();

    if (w < QT) {
        float v = (lane < NPTS) ? s.fc[w*NPTS + lane] : 0.f;
        #pragma unroll
        for (int o = 16; o; o >>= 1) v += __shfl_xor_sync(0xffffffffu, v, o);
        if (lane == 0) s.cls[w] = v * (1.0f / 25.0f);
    }
    if (t < QT*NGT) {
        int q = t >> 5, g = t & 31;
        float d0 = 0.f;
        #pragma unroll 8
        for (int v = 0; v < VOC; v++)
            d0 = fmaf(s.Ts[g*97 + v], s.logPs[q*VOC + v], d0);
        s.kls[t] = (s.sl[g] == 0) ? 100.0f : (s.stt[g] - d0);
    }
    __syncthreads();

    // ---- cdist (packed f32x2) + assemble output: thread t = column ----
    u64 acc2[4];
    #pragma unroll
    for (int p = 0; p < 4; p++) acc2[p] = pack2(s.cls[2*p], s.cls[2*p+1]);

    #pragma unroll
    for (int db = 0; db < 13; db++) {
        float4 tv = g_tgtT4[db*NCOLS + t];   // coalesced, L2/L1 resident
        u64 n0 = pack2(-tv.x, -tv.x);
        u64 n1 = pack2(-tv.y, -tv.y);
        u64 n2 = pack2(-tv.z, -tv.z);
        u64 n3 = pack2(-tv.w, -tv.w);
        #pragma unroll
        for (int p = 0; p < 4; p++) {
            const ulonglong2* row = (const ulonglong2*)&s.pp2[p*52 + db*4];
            ulonglong2 ra = row[0];       // (d0,d1) packed pairs
            ulonglong2 rb = row[1];       // (d2,d3)
            u64 d0 = add2(ra.x, n0) & ABSM;
            u64 d1 = add2(ra.y, n1) & ABSM;
            u64 d2 = add2(rb.x, n2) & ABSM;
            u64 d3 = add2(rb.y, n3) & ABSM;
            acc2[p] = add2(acc2[p], add2(add2(d0, d1), add2(d2, d3)));
        }
    }

    bool diag = ((t >> 5) == b);
    int  g    = t & 31;
    #pragma unroll
    for (int p = 0; p < 4; p++) {
        float lo, hi;
        unpack2(lo, hi, acc2[p]);
        int q = 2*p;
        out[(size_t)(b*NQ + q0 + q)*NCOLS + t]     = lo + (diag ? s.kls[q*NGT + g]     : 0.0f);
        out[(size_t)(b*NQ + q0 + q + 1)*NCOLS + t] = hi + (diag ? s.kls[(q+1)*NGT + g] : 0.0f);
    }
}

// -----------------------------------------------------------------------------
extern "C" void kernel_launch(void* const* d_in, const int* in_sizes, int n_in,
                              void* d_out, int out_size) {
    const float* pred_logits      = (const float*)d_in[0];
    const float* pred_ctrl_points = (const float*)d_in[1];
    const float* pred_text_logits = (const float*)d_in[2];
    const float* tgt_ctrl_points  = (const float*)d_in[3];
    const int*   tgt_texts        = (const int*)d_in[4];
    const float* centroids        = (const float*)d_in[5];
    float* out = (float*)d_out;

    static bool attr_done = false;
    if (!attr_done) {
        cudaFuncSetAttribute(k_main, cudaFuncAttributeMaxDynamicSharedMemorySize,
                             (int)sizeof(SmemMain));
        attr_done = true;
    }

    k_soft<<<VOC, 256>>>(centroids);
    k_T<<<NCOLS, VOC>>>(tgt_texts, tgt_ctrl_points);
    k_main<<<dim3(NQ/QT, BS), 512, sizeof(SmemMain)>>>(pred_text_logits, pred_logits,
                                                       pred_ctrl_points, out);
}

// round 5
// speedup vs baseline: 2.0782x; 1.2302x over previous
#include <cuda_runtime.h>

#define VOC   96
#define BS    16
#define NQ    200
#define NPTS  25
#define NGT   32
#define LSEQ  25
#define NCOLS (BS*NGT)      /* 512 */
#define CDIM  256
#define QT    8

typedef unsigned long long u64;
#define ABSM 0x7FFFFFFF7FFFFFFFULL

// ---------------- scratch (static device globals; no allocation) ------------
__device__ float  g_soft[VOC*VOC];
__device__ float  g_T[NCOLS*VOC];
__device__ float  g_sumTlogT[NCOLS];
__device__ int    g_len[NCOLS];
__device__ float4 g_tgtT4[13*NCOLS];        // transposed+padded tgt pts [dblk][col]

// ---------------- packed f32x2 helpers (Blackwell) --------------------------
__device__ __forceinline__ u64 pack2(float lo, float hi) {
    u64 r; asm("mov.b64 %0, {%1, %2};" : "=l"(r) : "f"(lo), "f"(hi)); return r;
}
__device__ __forceinline__ u64 add2(u64 a, u64 b) {
    u64 r; asm("add.rn.f32x2 %0, %1, %2;" : "=l"(r) : "l"(a), "l"(b)); return r;
}
__device__ __forceinline__ void unpack2(float& lo, float& hi, u64 a) {
    asm("mov.b64 {%0, %1}, %2;" : "=f"(lo), "=f"(hi) : "l"(a));
}

// ---------------- fast exp, FMA pipe only (magic rounding, no F2I/FRND) -----
__device__ __forceinline__ float fexp(float x) {
    x = fmaxf(x, -87.0f);
    float t = fmaf(x, 1.4426950408889634f, 12582912.0f);
    int   i = __float_as_int(t);
    float n = t - 12582912.0f;
    float f = fmaf(x, 1.4426950408889634f, -n);
    float p = 1.33335581e-3f;
    p = fmaf(p, f, 9.61812911e-3f);
    p = fmaf(p, f, 5.55041087e-2f);
    p = fmaf(p, f, 2.40226507e-1f);
    p = fmaf(p, f, 6.93147180e-1f);
    p = fmaf(p, f, 1.0f);
    return p * __int_as_float((i + 127) << 23);
}

// ---------------- kernel 1: soft_all [96,96], latency-batched ----------------
__global__ void __launch_bounds__(256) k_soft(const float* __restrict__ centroids) {
    __shared__ float ci[CDIM];
    __shared__ float srow[VOC], nrow[VOC];
    __shared__ float stage[VOC];
    __shared__ float bc[2];
    int i = blockIdx.x, t = threadIdx.x, w = t >> 5, lane = t & 31;

    ci[t] = centroids[i*CDIM + t];
    __syncthreads();

    // warp w owns j = w + 8*jj, jj<12; 12 independent dot/nrm chains (MLP)
    float dot[12], nrm[12];
    #pragma unroll
    for (int jj = 0; jj < 12; jj++) { dot[jj] = 0.f; nrm[jj] = 0.f; }
    #pragma unroll
    for (int u = 0; u < 8; u++) {
        float a = ci[lane + u*32];
        #pragma unroll
        for (int jj = 0; jj < 12; jj++) {
            float bvl = centroids[(w + 8*jj)*CDIM + lane + u*32];
            dot[jj] = fmaf(a,   bvl, dot[jj]);
            nrm[jj] = fmaf(bvl, bvl, nrm[jj]);
        }
    }
    #pragma unroll
    for (int o = 16; o; o >>= 1) {
        #pragma unroll
        for (int jj = 0; jj < 12; jj++) {
            dot[jj] += __shfl_xor_sync(0xffffffffu, dot[jj], o);
            nrm[jj] += __shfl_xor_sync(0xffffffffu, nrm[jj], o);
        }
    }
    // after xor-butterfly every lane holds the full sum; lane 0 publishes all 12
    if (lane == 0) {
        #pragma unroll
        for (int jj = 0; jj < 12; jj++) {
            srow[w + 8*jj] = dot[jj];
            nrow[w + 8*jj] = nrm[jj];
        }
    }
    __syncthreads();

    float ni = nrow[i];
    float sv = (t < VOC) ? srow[t] * rsqrtf(nrow[t] * ni) : -1e30f;
    if (t < VOC) stage[t] = sv;
    __syncthreads();
    if (w == 0) {
        float m = fmaxf(fmaxf(stage[lane], stage[lane+32]), stage[lane+64]);
        #pragma unroll
        for (int o = 16; o; o >>= 1) m = fmaxf(m, __shfl_xor_sync(0xffffffffu, m, o));
        if (lane == 0) bc[0] = m;
    }
    __syncthreads();
    float e = (t < VOC) ? fexp(sv - bc[0]) : 0.f;
    if (t < VOC) stage[t] = e;
    __syncthreads();
    if (w == 0) {
        float s = stage[lane] + stage[lane+32] + stage[lane+64];
        #pragma unroll
        for (int o = 16; o; o >>= 1) s += __shfl_xor_sync(0xffffffffu, s, o);
        if (lane == 0) bc[1] = s;
    }
    __syncthreads();
    if (t < VOC)
        g_soft[i*VOC + t] = (t == i ? 0.85f : 0.0f) + 0.15f * (e / bc[1]);
}

// ---------------- kernel 2: T, sum T log T, lengths, tgt transpose ----------
__global__ void k_T(const int* __restrict__ texts,
                    const float* __restrict__ tgtpts) {
    int bg = blockIdx.x;              // 0..511
    int t  = threadIdx.x;             // 96 threads
    __shared__ int   idx[LSEQ];
    __shared__ float red[VOC];
    __shared__ float b0;
    if (t < LSEQ) idx[t] = texts[bg*LSEQ + t];
    if (t < 52) {
        float v = (t < 50) ? tgtpts[bg*50 + t] : 0.0f;
        ((float*)g_tgtT4)[(size_t)((t >> 2)*NCOLS + bg)*4 + (t & 3)] = v;
    }
    __syncthreads();
    float acc = 0.f; int len = 0;
    #pragma unroll
    for (int l = 0; l < LSEQ; l++) {
        int id = idx[l];
        if (id != VOC) {
            int r = min(max(id, 0), VOC - 1);
            acc += g_soft[r*VOC + t];
            len++;
        }
    }
    float Tv = acc / (float)max(len, 1) + 1e-6f;
    red[t] = Tv;
    __syncthreads();
    if (t < 32) {
        float s = red[t] + red[t+32] + red[t+64];
        #pragma unroll
        for (int o = 16; o; o >>= 1) s += __shfl_xor_sync(0xffffffffu, s, o);
        if (t == 0) b0 = s;
    }
    __syncthreads();
    float Tn = Tv / b0;
    g_T[bg*VOC + t] = Tn;
    red[t] = Tn * __logf(Tn);
    __syncthreads();
    if (t < 32) {
        float s2 = red[t] + red[t+32] + red[t+64];
        #pragma unroll
        for (int o = 16; o; o >>= 1) s2 += __shfl_xor_sync(0xffffffffu, s2, o);
        if (t == 0) { g_sumTlogT[bg] = s2; g_len[bg] = len; }
    }
}

// ---------------- kernel 3: fused main (register softmax, 3 barriers) -------
__global__ void __launch_bounds__(512) k_main(const float* __restrict__ txt,
                                              const float* __restrict__ logits,
                                              const float* __restrict__ predpts,
                                              float* __restrict__ out) {
    __shared__ float  Pw[16][100];     // per-warp partial mean-prob
    __shared__ float  logPs[QT][VOC];
    __shared__ float2 pp2[4*52];
    __shared__ float  Ts[NGT*97];
    __shared__ float  stt[NGT];
    __shared__ int    sl[NGT];
    __shared__ float  cls[QT];
    __shared__ float  kls[QT*NGT];
    __shared__ float  fc[QT*NPTS];

    int b  = blockIdx.y;
    int q0 = blockIdx.x * QT;
    int t  = threadIdx.x;
    int w  = t >> 5, lane = t & 31;

    // ---- phase 0: side-data preload (no barrier needed before phase 1) ----
    for (int k = t; k < 4*52; k += 512) {
        int pair = k / 52, d = k - pair*52;
        float v0 = 0.f, v1 = 0.f;
        if (d < 50) {
            v0 = predpts[(size_t)(b*NQ + q0 + 2*pair)*50 + d];
            v1 = predpts[(size_t)(b*NQ + q0 + 2*pair + 1)*50 + d];
        }
        pp2[k] = make_float2(v0, v1);
    }
    for (int k = t; k < NGT*VOC; k += 512) {
        int g = k / VOC, v = k - g*VOC;
        Ts[g*97 + v] = g_T[(size_t)b*NGT*VOC + k];
    }
    if (t < NGT) { stt[t] = g_sumTlogT[b*NGT + t]; sl[t] = g_len[b*NGT + t]; }
    if (t < QT*NPTS) {
        float x  = logits[(size_t)(b*NQ + q0)*NPTS + t];
        float pr = 1.0f / (1.0f + fexp(-x));
        float pos = 0.25f * (1.f - pr) * (1.f - pr) * (-__logf(pr + 1e-8f));
        float neg = 0.75f * pr * pr * (-__logf(1.f - pr + 1e-8f));
        fc[t] = pos - neg;
    }

    // ---- phase 1: register softmax; 2 warps per query, rows from GLOBAL ----
    {
        int q = w >> 1;
        const float* base = txt + (size_t)(b*NQ + q0 + q) * NPTS * (VOC + 1);
        float pv0 = 0.f, pv1 = 0.f, pv2 = 0.f;
        for (int p = (w & 1); p < NPTS; p += 2) {
            const float* row = base + p*(VOC + 1);
            float x0 = row[lane];
            float x1 = row[lane + 32];
            float x2 = row[lane + 64];
            float x3 = (lane == 0) ? row[96] : -1e30f;
            float m = fmaxf(fmaxf(x0, x1), fmaxf(x2, x3));
            #pragma unroll
            for (int o = 16; o; o >>= 1) m = fmaxf(m, __shfl_xor_sync(0xffffffffu, m, o));
            float e0 = fexp(x0 - m), e1 = fexp(x1 - m), e2 = fexp(x2 - m);
            float e3 = (lane == 0) ? fexp(x3 - m) : 0.f;
            float sm = e0 + e1 + e2 + e3;
            #pragma unroll
            for (int o = 16; o; o >>= 1) sm += __shfl_xor_sync(0xffffffffu, sm, o);
            float inv = 1.0f / sm;
            pv0 = fmaf(e0, inv, pv0);
            pv1 = fmaf(e1, inv, pv1);
            pv2 = fmaf(e2, inv, pv2);
        }
        Pw[w][lane]      = pv0;
        Pw[w][lane + 32] = pv1;
        Pw[w][lane + 64] = pv2;
    }
    __syncthreads();

    // ---- phase 2: per-query normalize + logP (warps 0..7); cls (warps 8..15)
    if (w < QT) {
        float a0 = (Pw[2*w][lane]    + Pw[2*w+1][lane])    * (1.0f/25.0f) + 1e-6f;
        float a1 = (Pw[2*w][lane+32] + Pw[2*w+1][lane+32]) * (1.0f/25.0f) + 1e-6f;
        float a2 = (Pw[2*w][lane+64] + Pw[2*w+1][lane+64]) * (1.0f/25.0f) + 1e-6f;
        float sm = a0 + a1 + a2;
        #pragma unroll
        for (int o = 16; o; o >>= 1) sm += __shfl_xor_sync(0xffffffffu, sm, o);
        float inv = 1.0f / sm;
        logPs[w][lane]      = __logf(a0 * inv);
        logPs[w][lane + 32] = __logf(a1 * inv);
        logPs[w][lane + 64] = __logf(a2 * inv);
    } else if (w < 8 + QT) {
        int q = w - 8;
        float v = (lane < NPTS) ? fc[q*NPTS + lane] : 0.f;
        #pragma unroll
        for (int o = 16; o; o >>= 1) v += __shfl_xor_sync(0xffffffffu, v, o);
        if (lane == 0) cls[q] = v * (1.0f / 25.0f);
    }
    __syncthreads();

    // ---- phase 3: KL over all 512 threads (2 threads per (q,g) pair) ----
    {
        int pid = t >> 1, h = t & 1;
        int q = pid >> 5, g = pid & 31;
        float d0 = 0.f;
        const float* tr = &Ts[g*97 + h*48];
        const float* lr = &logPs[q][h*48];
        #pragma unroll 8
        for (int v = 0; v < 48; v++)
            d0 = fmaf(tr[v], lr[v], d0);
        d0 += __shfl_xor_sync(0xffffffffu, d0, 1);
        if (h == 0) kls[pid] = (sl[g] == 0) ? 100.0f : (stt[g] - d0);
    }
    __syncthreads();

    // ---- phase 4: cdist (packed f32x2) + output ----
    u64 acc2[4];
    #pragma unroll
    for (int p = 0; p < 4; p++) acc2[p] = pack2(cls[2*p], cls[2*p+1]);

    #pragma unroll
    for (int db = 0; db < 13; db++) {
        float4 tv = g_tgtT4[db*NCOLS + t];
        u64 n0 = pack2(-tv.x, -tv.x);
        u64 n1 = pack2(-tv.y, -tv.y);
        u64 n2 = pack2(-tv.z, -tv.z);
        u64 n3 = pack2(-tv.w, -tv.w);
        #pragma unroll
        for (int p = 0; p < 4; p++) {
            const ulonglong2* row = (const ulonglong2*)&pp2[p*52 + db*4];
            ulonglong2 ra = row[0];
            ulonglong2 rb = row[1];
            u64 d0 = add2(ra.x, n0) & ABSM;
            u64 d1 = add2(ra.y, n1) & ABSM;
            u64 d2 = add2(rb.x, n2) & ABSM;
            u64 d3 = add2(rb.y, n3) & ABSM;
            acc2[p] = add2(acc2[p], add2(add2(d0, d1), add2(d2, d3)));
        }
    }

    bool diag = ((t >> 5) == b);
    int  g    = t & 31;
    #pragma unroll
    for (int p = 0; p < 4; p++) {
        float lo, hi;
        unpack2(lo, hi, acc2[p]);
        int q = 2*p;
        out[(size_t)(b*NQ + q0 + q)*NCOLS + t]     = lo + (diag ? kls[q*NGT + g]     : 0.0f);
        out[(size_t)(b*NQ + q0 + q + 1)*NCOLS + t] = hi + (diag ? kls[(q+1)*NGT + g] : 0.0f);
    }
}

// -----------------------------------------------------------------------------
extern "C" void kernel_launch(void* const* d_in, const int* in_sizes, int n_in,
                              void* d_out, int out_size) {
    const float* pred_logits      = (const float*)d_in[0];
    const float* pred_ctrl_points = (const float*)d_in[1];
    const float* pred_text_logits = (const float*)d_in[2];
    const float* tgt_ctrl_points  = (const float*)d_in[3];
    const int*   tgt_texts        = (const int*)d_in[4];
    const float* centroids        = (const float*)d_in[5];
    float* out = (float*)d_out;

    k_soft<<<VOC, 256>>>(centroids);
    k_T<<<NCOLS, VOC>>>(tgt_texts, tgt_ctrl_points);
    k_main<<<dim3(NQ/QT, BS), 512>>>(pred_text_logits, pred_logits,
                                     pred_ctrl_points, out);
}